// round 5
// baseline (speedup 1.0000x reference)
#include <cuda_runtime.h>
#include <cuda_fp16.h>
#include <cstdint>

// ---------------- problem dims ----------------
#define M_DIM 4096
#define K_DIM 4096
#define N_DIM 16384

// ================= scratch (no cudaMalloc allowed) =================
__device__ __align__(256) __half g_A[(size_t)M_DIM * K_DIM];   // 32 MB fp16 x
__device__ __align__(256) __half g_B[(size_t)N_DIM * K_DIM];   // 128 MB fp16 w

// ---------------- helpers ----------------
__device__ __forceinline__ uint32_t smem_u32(const void* p) {
    uint32_t a;
    asm("{ .reg .u64 t; cvta.to.shared.u64 t, %1; cvt.u32.u64 %0, t; }"
        : "=r"(a) : "l"(p));
    return a;
}

#define SWZ128(x) ((x) ^ (((x) >> 3) & 0x70))

#define CP_ASYNC16(dst, src) \
    asm volatile("cp.async.cg.shared.global [%0], [%1], 16;" \
                 :: "r"((uint32_t)(dst)), "l"(src) : "memory")
#define CP_COMMIT() asm volatile("cp.async.commit_group;" ::: "memory")
#define CP_WAIT(n)  asm volatile("cp.async.wait_group %0;" :: "n"(n) : "memory")

// ================= prepass =================
// x: fp32 -> fp16
__global__ void __launch_bounds__(256) cvt_x_kernel(const float* __restrict__ x) {
    size_t gid = (size_t)blockIdx.x * blockDim.x + threadIdx.x;   // M*K/8 threads
    const float4* s = (const float4*)x + gid * 2;
    float4 a = s[0], b = s[1];
    __half2 h0 = __floats2half2_rn(a.x, a.y);
    __half2 h1 = __floats2half2_rn(a.z, a.w);
    __half2 h2 = __floats2half2_rn(b.x, b.y);
    __half2 h3 = __floats2half2_rn(b.z, b.w);
    uint4 o;
    o.x = *(uint32_t*)&h0; o.y = *(uint32_t*)&h1;
    o.z = *(uint32_t*)&h2; o.w = *(uint32_t*)&h3;
    ((uint4*)g_A)[gid] = o;
}

// weight_q: delivered by the harness as INT32 (one sign-extended int8 per word).
// N*K int32 values -> fp16 (exact).
__global__ void __launch_bounds__(256) cvt_w_kernel(const int* __restrict__ w) {
    size_t gid = (size_t)blockIdx.x * blockDim.x + threadIdx.x;   // N*K/8 threads
    const int4* s = (const int4*)w + gid * 2;
    int4 v0 = s[0], v1 = s[1];
    __half2 p0 = __halves2half2(__float2half_rn((float)v0.x), __float2half_rn((float)v0.y));
    __half2 p1 = __halves2half2(__float2half_rn((float)v0.z), __float2half_rn((float)v0.w));
    __half2 p2 = __halves2half2(__float2half_rn((float)v1.x), __float2half_rn((float)v1.y));
    __half2 p3 = __halves2half2(__float2half_rn((float)v1.z), __float2half_rn((float)v1.w));
    uint4 o;
    o.x = *(uint32_t*)&p0; o.y = *(uint32_t*)&p1;
    o.z = *(uint32_t*)&p2; o.w = *(uint32_t*)&p3;
    ((uint4*)g_B)[gid] = o;
}

// =====================================================================
// GEMM: cp.async + ldmatrix + mma.sync.m16n8k16 (plain sm_103 legal)
// CTA tile 128(M) x 256(N) x 64(K), 4-stage pipeline, 8 warps (2 M x 4 N),
// warp tile 64x64.
// =====================================================================
#define H_TM 128
#define H_TN 256
#define H_TK 64
#define H_KTILES (K_DIM / H_TK)
#define H_STAGES 4
#define HA_BYTES (H_TM * H_TK * 2)   // 16384
#define HB_BYTES (H_TN * H_TK * 2)   // 32768
#define H_STAGE (HA_BYTES + HB_BYTES)
#define H_SMEM (H_STAGES * H_STAGE)  // 196608

__global__ void __launch_bounds__(256, 1)
gemm_hmma(const float* __restrict__ scale, const float* __restrict__ bias,
          float* __restrict__ out) {
    extern __shared__ __align__(1024) char smem[];
    const uint32_t sb = smem_u32(smem);
    const int tid = threadIdx.x;
    const int lane = tid & 31;
    const int wid = tid >> 5;
    const int wm = wid & 1;           // 2 warps along M
    const int wn = wid >> 1;          // 4 warps along N

    const int nTN = N_DIM / H_TN;     // 64
    const int GROUPM = 8;
    const int npg = GROUPM * nTN;
    int pid = blockIdx.x;
    int grp = pid / npg;
    int inp = pid - grp * npg;
    int tm = grp * GROUPM + (inp % GROUPM);
    int tn = inp / GROUPM;

    const char* gA = (const char*)(g_A + (size_t)tm * H_TM * K_DIM);
    const char* gB = (const char*)(g_B + (size_t)tn * H_TN * K_DIM);

    auto load_stage = [&](int s, int kt) {
        uint32_t sa = sb + s * H_STAGE;
        uint32_t sB = sa + HA_BYTES;
        size_t kofs = (size_t)kt * 128;          // 64 halves = 128B
#pragma unroll
        for (int i = 0; i < 4; i++) {            // A: 128 rows x 8 chunks
            int c = tid + 256 * i;
            int row = c >> 3;
            int col = (c & 7) * 16;
            CP_ASYNC16(sa + SWZ128(row * 128 + col),
                       gA + (size_t)row * (K_DIM * 2) + kofs + col);
        }
#pragma unroll
        for (int i = 0; i < 8; i++) {            // B: 256 rows x 8 chunks
            int c = tid + 256 * i;
            int row = c >> 3;
            int col = (c & 7) * 16;
            CP_ASYNC16(sB + SWZ128(row * 128 + col),
                       gB + (size_t)row * (K_DIM * 2) + kofs + col);
        }
        CP_COMMIT();
    };

    float acc[4][8][4];
#pragma unroll
    for (int i = 0; i < 4; i++)
#pragma unroll
        for (int j = 0; j < 8; j++)
#pragma unroll
            for (int k = 0; k < 4; k++) acc[i][j][k] = 0.f;

    // ldmatrix lane-address components
    const int a_row = lane & 15;                        // A rows within 16
    const int a_col = (lane >> 4) * 16;                 // k halves 0-7 / 8-15
    const int b_row = (lane & 7) + ((lane >> 4) << 3);  // n within 16
    const int b_col = ((lane >> 3) & 1) * 16;           // k bytes 0 / 16

    load_stage(0, 0);
    load_stage(1, 1);
    load_stage(2, 2);

    for (int kt = 0; kt < H_KTILES; kt++) {
        if (kt + 1 >= H_KTILES)      { CP_WAIT(0); }
        else if (kt + 2 >= H_KTILES) { CP_WAIT(1); }
        else                         { CP_WAIT(2); }
        __syncthreads();
        if (kt + 3 < H_KTILES) load_stage((kt + 3) & 3, kt + 3);

        uint32_t sa = sb + (kt & 3) * H_STAGE;
        uint32_t sB = sa + HA_BYTES;
#pragma unroll
        for (int ks = 0; ks < 4; ks++) {
            uint32_t a[4][4];
#pragma unroll
            for (int mt = 0; mt < 4; mt++) {
                int row = wm * 64 + mt * 16 + a_row;
                int colb = ks * 32 + a_col;
                uint32_t addr = sa + SWZ128(row * 128 + colb);
                asm volatile(
                    "ldmatrix.sync.aligned.m8n8.x4.shared.b16 {%0,%1,%2,%3}, [%4];"
                    : "=r"(a[mt][0]), "=r"(a[mt][1]), "=r"(a[mt][2]), "=r"(a[mt][3])
                    : "r"(addr));
            }
            uint32_t b[4][4];
#pragma unroll
            for (int nt2 = 0; nt2 < 4; nt2++) {
                int row = wn * 64 + nt2 * 16 + b_row;
                int colb = ks * 32 + b_col;
                uint32_t addr = sB + SWZ128(row * 128 + colb);
                asm volatile(
                    "ldmatrix.sync.aligned.m8n8.x4.shared.b16 {%0,%1,%2,%3}, [%4];"
                    : "=r"(b[nt2][0]), "=r"(b[nt2][1]), "=r"(b[nt2][2]), "=r"(b[nt2][3])
                    : "r"(addr));
            }
#pragma unroll
            for (int mt = 0; mt < 4; mt++) {
#pragma unroll
                for (int nt = 0; nt < 8; nt++) {
                    uint32_t b0 = (nt & 1) ? b[nt >> 1][2] : b[nt >> 1][0];
                    uint32_t b1 = (nt & 1) ? b[nt >> 1][3] : b[nt >> 1][1];
                    asm volatile(
                        "mma.sync.aligned.m16n8k16.row.col.f32.f16.f16.f32 "
                        "{%0,%1,%2,%3}, {%4,%5,%6,%7}, {%8,%9}, {%0,%1,%2,%3};"
                        : "+f"(acc[mt][nt][0]), "+f"(acc[mt][nt][1]),
                          "+f"(acc[mt][nt][2]), "+f"(acc[mt][nt][3])
                        : "r"(a[mt][0]), "r"(a[mt][1]), "r"(a[mt][2]), "r"(a[mt][3]),
                          "r"(b0), "r"(b1));
                }
            }
        }
    }

    // ---- epilogue: fuse per-channel scale + bias ----
    float2 sc2[8], bi2[8];
#pragma unroll
    for (int nt = 0; nt < 8; nt++) {
        int cn = tn * H_TN + wn * 64 + nt * 8 + 2 * (lane & 3);
        sc2[nt] = *(const float2*)(scale + cn);
        bi2[nt] = *(const float2*)(bias + cn);
    }
#pragma unroll
    for (int mt = 0; mt < 4; mt++) {
        int r0 = tm * H_TM + wm * 64 + mt * 16 + (lane >> 2);
        int r1 = r0 + 8;
#pragma unroll
        for (int nt = 0; nt < 8; nt++) {
            int cn = tn * H_TN + wn * 64 + nt * 8 + 2 * (lane & 3);
            float2 o0, o1;
            o0.x = acc[mt][nt][0] * sc2[nt].x + bi2[nt].x;
            o0.y = acc[mt][nt][1] * sc2[nt].y + bi2[nt].y;
            o1.x = acc[mt][nt][2] * sc2[nt].x + bi2[nt].x;
            o1.y = acc[mt][nt][3] * sc2[nt].y + bi2[nt].y;
            *(float2*)(out + (size_t)r0 * N_DIM + cn) = o0;
            *(float2*)(out + (size_t)r1 * N_DIM + cn) = o1;
        }
    }
}

// ---------------- launch ----------------
extern "C" void kernel_launch(void* const* d_in, const int* in_sizes, int n_in,
                              void* d_out, int out_size) {
    const float* x     = (const float*)d_in[0];
    const int*   w     = (const int*)d_in[1];   // int8 values shipped as int32
    const float* scale = (const float*)d_in[2];
    const float* bias  = (const float*)d_in[3];
    float*       out   = (float*)d_out;

    cudaFuncSetAttribute(gemm_hmma,
                         cudaFuncAttributeMaxDynamicSharedMemorySize, H_SMEM);

    cvt_x_kernel<<<(int)((size_t)M_DIM * K_DIM / 8 / 256), 256>>>(x);
    cvt_w_kernel<<<(int)((size_t)N_DIM * K_DIM / 8 / 256), 256>>>(w);
    gemm_hmma<<<(M_DIM / H_TM) * (N_DIM / H_TN), 256, H_SMEM>>>(scale, bias, out);
}